// round 2
// baseline (speedup 1.0000x reference)
#include <cuda_runtime.h>
#include <cuda_bf16.h>
#include <cstdio>

// Problem constants
#define N0 100000
#define N1 25000
#define N2 6250
#define E0 1600000
#define E1 400000
#define E2 100000
#define NF 128
#define NH 128
#define NC 40

// ---------------------------------------------------------------------------
// Scratch (device globals — no allocation allowed)
// ---------------------------------------------------------------------------
__device__ __align__(16) float g_xW[(size_t)N0 * NH];     // x @ gc1_W
__device__ __align__(16) float g_p1[(size_t)N1 * NH];     // pooled level 1
__device__ __align__(16) float g_q1[(size_t)N1 * NH];
__device__ __align__(16) float g_k1[(size_t)N1 * NH];
__device__ __align__(16) float g_h01[(size_t)N1 * NH];    // p1 + emb[nwgt1]
__device__ __align__(16) float g_msg1[(size_t)N1 * NH];
__device__ __align__(16) float g_c1[(size_t)N1 * NH];     // crf1 output
__device__ __align__(16) float g_u1[(size_t)N1 * NH];     // unpool level1
__device__ __align__(16) float g_p2[(size_t)N2 * NH];
__device__ __align__(16) float g_q2[(size_t)N2 * NH];
__device__ __align__(16) float g_k2[(size_t)N2 * NH];
__device__ __align__(16) float g_h02[(size_t)N2 * NH];
__device__ __align__(16) float g_msg2[(size_t)N2 * NH];
__device__ __align__(16) float g_c2[(size_t)N2 * NH];
__device__ __align__(16) float g_hW2[(size_t)N0 * NC];    // crf_hidden @ gc2_W
__device__ float g_logit1[E1];
__device__ float g_z1[N1];
__device__ unsigned g_max1[N1];
__device__ float g_logit2[E2];
__device__ float g_z2[N2];
__device__ unsigned g_max2[N2];

// ---------------------------------------------------------------------------
// Helpers
// ---------------------------------------------------------------------------
__device__ __forceinline__ unsigned f2ord(float f) {
    unsigned u = __float_as_uint(f);
    return (u & 0x80000000u) ? ~u : (u | 0x80000000u);
}
__device__ __forceinline__ float ord2f(unsigned u) {
    return __uint_as_float((u & 0x80000000u) ? (u & 0x7FFFFFFFu) : ~u);
}
__device__ __forceinline__ void red_add_v4(float4* addr, float a, float b, float c, float d) {
    asm volatile("red.global.add.v4.f32 [%0], {%1, %2, %3, %4};"
                 :: "l"(addr), "f"(a), "f"(b), "f"(c), "f"(d) : "memory");
}

// ---------------------------------------------------------------------------
// Generic tiled SGEMM: C[M,N] = A[M,K] @ B[K,N]
// ---------------------------------------------------------------------------
#define GBM 64
#define GBN 64
#define GBK 16
#define GTM 4
#define GTN 4
__global__ void sgemm_k(const float* __restrict__ A, const float* __restrict__ B,
                        float* __restrict__ C, int M, int N, int K) {
    __shared__ float As[GBM][GBK + 1];
    __shared__ float Bs[GBK][GBN + 1];
    int tid = threadIdx.x;                 // 256 threads
    int tcol = tid % (GBN / GTN);          // 0..15
    int trow = tid / (GBN / GTN);          // 0..15
    int rowBase = blockIdx.y * GBM;
    int colBase = blockIdx.x * GBN;
    float acc[GTM][GTN] = {};
    for (int k0 = 0; k0 < K; k0 += GBK) {
        for (int i = tid; i < GBM * GBK; i += 256) {
            int r = i / GBK, c = i % GBK;
            int gr = rowBase + r;
            As[r][c] = (gr < M) ? A[(size_t)gr * K + k0 + c] : 0.f;
        }
        for (int i = tid; i < GBK * GBN; i += 256) {
            int r = i / GBN, c = i % GBN;
            int gc = colBase + c;
            Bs[r][c] = (gc < N) ? B[(size_t)(k0 + r) * N + gc] : 0.f;
        }
        __syncthreads();
#pragma unroll
        for (int kk = 0; kk < GBK; kk++) {
            float a[GTM], b[GTN];
#pragma unroll
            for (int i = 0; i < GTM; i++) a[i] = As[trow * GTM + i][kk];
#pragma unroll
            for (int j = 0; j < GTN; j++) b[j] = Bs[kk][tcol * GTN + j];
#pragma unroll
            for (int i = 0; i < GTM; i++)
#pragma unroll
                for (int j = 0; j < GTN; j++) acc[i][j] += a[i] * b[j];
        }
        __syncthreads();
    }
#pragma unroll
    for (int i = 0; i < GTM; i++) {
        int gr = rowBase + trow * GTM + i;
        if (gr >= M) continue;
#pragma unroll
        for (int j = 0; j < GTN; j++) {
            int gc = colBase + tcol * GTN + j;
            if (gc < N) C[(size_t)gr * N + gc] = acc[i][j];
        }
    }
}

// ---------------------------------------------------------------------------
// Elementwise / init kernels
// ---------------------------------------------------------------------------
__global__ void init_bias_k(float* __restrict__ Y, const float* __restrict__ b,
                            int total, int N) {
    int i = blockIdx.x * blockDim.x + threadIdx.x;
    if (i < total) Y[i] = b[i % N];
}
__global__ void relu_k(float* __restrict__ Y, int total) {
    int i = blockIdx.x * blockDim.x + threadIdx.x;
    if (i < total) Y[i] = fmaxf(Y[i], 0.f);
}
__global__ void add_emb_k(const float* __restrict__ X, const float* __restrict__ emb,
                          const int* __restrict__ nw, float* __restrict__ H0, int M) {
    int i = blockIdx.x * blockDim.x + threadIdx.x;
    if (i >= M * NH) return;
    int r = i >> 7, c = i & 127;
    H0[i] = X[i] + emb[nw[r] * NH + c];
}
__global__ void combine_k(const float* __restrict__ H0, const float* __restrict__ MSG,
                          const float* __restrict__ pa, const float* __restrict__ pb,
                          float* __restrict__ OUT, int total) {
    int i = blockIdx.x * blockDim.x + threadIdx.x;
    if (i >= total) return;
    float a = *pa, b = *pb;
    OUT[i] = (a * H0[i] + b * MSG[i]) / (a + b);
}
__global__ void unpool_add_k(const float* __restrict__ UP, const int* __restrict__ assign,
                             const float* __restrict__ SKIP, float* __restrict__ OUT, int M) {
    int i = blockIdx.x * blockDim.x + threadIdx.x;
    if (i >= M * NH) return;
    int r = i >> 7, c = i & 127;
    OUT[i] = UP[(size_t)assign[r] * NH + c] + SKIP[i];
}

// ---------------------------------------------------------------------------
// Scatter kernels (COO SpMM / segment sums via vector reductions)
// ---------------------------------------------------------------------------
__global__ void spmm_scatter128(const int* __restrict__ dsts, const int* __restrict__ srcs,
                                const float* __restrict__ val, const float* __restrict__ X,
                                float* __restrict__ Y, int E) {
    int w = (blockIdx.x * blockDim.x + threadIdx.x) >> 5;
    int lane = threadIdx.x & 31;
    if (w >= E) return;
    int dst = dsts[w], src = srcs[w];
    float v = val[w];
    float4 a = ((const float4*)(X + (size_t)src * NH))[lane];
    float4* yd = ((float4*)(Y + (size_t)dst * NH)) + lane;
    red_add_v4(yd, a.x * v, a.y * v, a.z * v, a.w * v);
}
__global__ void pool128(const float* __restrict__ X, const int* __restrict__ assign,
                        float* __restrict__ Y, int M) {
    int w = (blockIdx.x * blockDim.x + threadIdx.x) >> 5;
    int lane = threadIdx.x & 31;
    if (w >= M) return;
    int dst = assign[w];
    float4 a = ((const float4*)(X + (size_t)w * NH))[lane];
    float4* yd = ((float4*)(Y + (size_t)dst * NH)) + lane;
    red_add_v4(yd, a.x, a.y, a.z, a.w);
}
__global__ void spmm_scatter40(const int* __restrict__ dsts, const int* __restrict__ srcs,
                               const float* __restrict__ val, const float* __restrict__ X,
                               float* __restrict__ Y, int E) {
    int t = blockIdx.x * blockDim.x + threadIdx.x;
    if (t >= E * 10) return;
    int e = t / 10, c = t - e * 10;
    int dst = dsts[e], src = srcs[e];
    float v = val[e];
    float4 a = ((const float4*)(X + (size_t)src * NC))[c];
    float4* yd = ((float4*)(Y + (size_t)dst * NC)) + c;
    red_add_v4(yd, a.x * v, a.y * v, a.z * v, a.w * v);
}

// ---------------------------------------------------------------------------
// CRF edge kernels
// ---------------------------------------------------------------------------
__global__ void edge_logits_k(const int* __restrict__ dsts, const int* __restrict__ srcs,
                              const float* __restrict__ Q, const float* __restrict__ Km,
                              float* __restrict__ logit, unsigned* __restrict__ mx, int E) {
    int w = (blockIdx.x * blockDim.x + threadIdx.x) >> 5;
    int lane = threadIdx.x & 31;
    if (w >= E) return;
    int dst = dsts[w], src = srcs[w];
    float4 q = ((const float4*)(Q + (size_t)dst * NH))[lane];
    float4 k = ((const float4*)(Km + (size_t)src * NH))[lane];
    float acc = q.x * k.x + q.y * k.y + q.z * k.z + q.w * k.w;
#pragma unroll
    for (int o = 16; o; o >>= 1) acc += __shfl_xor_sync(0xFFFFFFFFu, acc, o);
    if (lane == 0) {
        float l = acc * 0.08838834764831845f;   // 1/sqrt(128)
        logit[w] = l;
        atomicMax(mx + dst, f2ord(l));
    }
}
__global__ void edge_expsum_k(const int* __restrict__ dsts, float* __restrict__ logit,
                              const unsigned* __restrict__ mx, float* __restrict__ z, int E) {
    int e = blockIdx.x * blockDim.x + threadIdx.x;
    if (e >= E) return;
    int dst = dsts[e];
    float m = ord2f(mx[dst]);
    float ex = __expf(logit[e] - m);
    logit[e] = ex;
    atomicAdd(z + dst, ex);
}
__global__ void edge_msg_k(const int* __restrict__ dsts, const int* __restrict__ srcs,
                           const float* __restrict__ ev, const float* __restrict__ z,
                           const float* __restrict__ H0, float* __restrict__ MSG, int E) {
    int w = (blockIdx.x * blockDim.x + threadIdx.x) >> 5;
    int lane = threadIdx.x & 31;
    if (w >= E) return;
    int dst = dsts[w], src = srcs[w];
    float c = ev[w] / (z[dst] + 1e-16f);
    float4 a = ((const float4*)(H0 + (size_t)src * NH))[lane];
    float4* yd = ((float4*)(MSG + (size_t)dst * NH)) + lane;
    red_add_v4(yd, a.x * c, a.y * c, a.z * c, a.w * c);
}

// ---------------------------------------------------------------------------
// Host launch
// ---------------------------------------------------------------------------
static inline int cdiv(long long a, long long b) { return (int)((a + b - 1) / b); }

extern "C" void kernel_launch(void* const* d_in, const int* in_sizes, int n_in,
                              void* d_out, int out_size) {
    const float* x       = (const float*)d_in[0];
    const int*   A0      = (const int*)d_in[1];
    const float* A0v     = (const float*)d_in[2];
    const int*   A1      = (const int*)d_in[3];
    const float* A1v     = (const float*)d_in[4];
    const int*   A2      = (const int*)d_in[5];
    const float* A2v     = (const float*)d_in[6];
    const int*   assign0 = (const int*)d_in[7];
    const int*   assign1 = (const int*)d_in[8];
    const int*   nwgt1   = (const int*)d_in[9];
    const int*   nwgt2   = (const int*)d_in[10];
    const float* gc1_W   = (const float*)d_in[11];
    const float* gc1_b   = (const float*)d_in[12];
    const float* gc2_W   = (const float*)d_in[13];
    const float* gc2_b   = (const float*)d_in[14];
    const float* c1Wq    = (const float*)d_in[15];
    const float* c1Wk    = (const float*)d_in[16];
    const float* c1emb   = (const float*)d_in[17];
    const float* c1a     = (const float*)d_in[18];
    const float* c1b     = (const float*)d_in[19];
    const float* c2Wq    = (const float*)d_in[20];
    const float* c2Wk    = (const float*)d_in[21];
    const float* c2emb   = (const float*)d_in[22];
    const float* c2a     = (const float*)d_in[23];
    const float* c2b     = (const float*)d_in[24];

    float* out = (float*)d_out;                       // [N0, NC]
    float* gcn = out + (size_t)N0 * NC;               // [N0, NH] gcn_hidden
    float* crf = gcn + (size_t)N0 * NH;               // [N0, NH] crf_hidden

    // scratch symbol addresses
    void *p_xW, *p_p1, *p_q1, *p_k1, *p_h01, *p_msg1, *p_c1, *p_u1;
    void *p_p2, *p_q2, *p_k2, *p_h02, *p_msg2, *p_c2, *p_hW2;
    void *p_l1, *p_z1, *p_m1, *p_l2, *p_z2, *p_m2;
    cudaGetSymbolAddress(&p_xW, g_xW);   cudaGetSymbolAddress(&p_p1, g_p1);
    cudaGetSymbolAddress(&p_q1, g_q1);   cudaGetSymbolAddress(&p_k1, g_k1);
    cudaGetSymbolAddress(&p_h01, g_h01); cudaGetSymbolAddress(&p_msg1, g_msg1);
    cudaGetSymbolAddress(&p_c1, g_c1);   cudaGetSymbolAddress(&p_u1, g_u1);
    cudaGetSymbolAddress(&p_p2, g_p2);   cudaGetSymbolAddress(&p_q2, g_q2);
    cudaGetSymbolAddress(&p_k2, g_k2);   cudaGetSymbolAddress(&p_h02, g_h02);
    cudaGetSymbolAddress(&p_msg2, g_msg2); cudaGetSymbolAddress(&p_c2, g_c2);
    cudaGetSymbolAddress(&p_hW2, g_hW2);
    cudaGetSymbolAddress(&p_l1, g_logit1); cudaGetSymbolAddress(&p_z1, g_z1);
    cudaGetSymbolAddress(&p_m1, g_max1);
    cudaGetSymbolAddress(&p_l2, g_logit2); cudaGetSymbolAddress(&p_z2, g_z2);
    cudaGetSymbolAddress(&p_m2, g_max2);

    float* xW  = (float*)p_xW;  float* p1 = (float*)p_p1;  float* q1 = (float*)p_q1;
    float* k1  = (float*)p_k1;  float* h01 = (float*)p_h01; float* msg1 = (float*)p_msg1;
    float* c1  = (float*)p_c1;  float* u1 = (float*)p_u1;
    float* p2  = (float*)p_p2;  float* q2 = (float*)p_q2;  float* k2 = (float*)p_k2;
    float* h02 = (float*)p_h02; float* msg2 = (float*)p_msg2; float* c2 = (float*)p_c2;
    float* hW2 = (float*)p_hW2;
    float* l1 = (float*)p_l1; float* z1 = (float*)p_z1; unsigned* m1 = (unsigned*)p_m1;
    float* l2 = (float*)p_l2; float* z2 = (float*)p_z2; unsigned* m2 = (unsigned*)p_m2;

    const int TB = 256;

    // ---- GCN layer 1: h = relu(A0 @ (x @ W1) + b1) -> gcn_hidden ----
    {
        dim3 g(cdiv(NH, GBN), cdiv(N0, GBM));
        sgemm_k<<<g, TB>>>(x, gc1_W, xW, N0, NH, NF);
    }
    init_bias_k<<<cdiv((long long)N0 * NH, TB), TB>>>(gcn, gc1_b, N0 * NH, NH);
    spmm_scatter128<<<cdiv((long long)E0 * 32, TB), TB>>>(A0, A0 + E0, A0v, xW, gcn, E0);
    relu_k<<<cdiv((long long)N0 * NH, TB), TB>>>(gcn, N0 * NH);

    // ---- level 1: pool + CRF ----
    cudaMemsetAsync(p1, 0, (size_t)N1 * NH * 4);
    pool128<<<cdiv((long long)N0 * 32, TB), TB>>>(gcn, assign0, p1, N0);
    {
        dim3 g(cdiv(NH, GBN), cdiv(N1, GBM));
        sgemm_k<<<g, TB>>>(p1, c1Wq, q1, N1, NH, NH);
        sgemm_k<<<g, TB>>>(p1, c1Wk, k1, N1, NH, NH);
    }
    add_emb_k<<<cdiv((long long)N1 * NH, TB), TB>>>(p1, c1emb, nwgt1, h01, N1);
    cudaMemsetAsync(m1, 0, N1 * 4);
    cudaMemsetAsync(z1, 0, N1 * 4);
    cudaMemsetAsync(msg1, 0, (size_t)N1 * NH * 4);
    edge_logits_k<<<cdiv((long long)E1 * 32, TB), TB>>>(A1, A1 + E1, q1, k1, l1, m1, E1);
    edge_expsum_k<<<cdiv(E1, TB), TB>>>(A1, l1, m1, z1, E1);
    edge_msg_k<<<cdiv((long long)E1 * 32, TB), TB>>>(A1, A1 + E1, l1, z1, h01, msg1, E1);
    combine_k<<<cdiv((long long)N1 * NH, TB), TB>>>(h01, msg1, c1a, c1b, c1, N1 * NH);

    // ---- level 2: pool + CRF ----
    cudaMemsetAsync(p2, 0, (size_t)N2 * NH * 4);
    pool128<<<cdiv((long long)N1 * 32, TB), TB>>>(c1, assign1, p2, N1);
    {
        dim3 g(cdiv(NH, GBN), cdiv(N2, GBM));
        sgemm_k<<<g, TB>>>(p2, c2Wq, q2, N2, NH, NH);
        sgemm_k<<<g, TB>>>(p2, c2Wk, k2, N2, NH, NH);
    }
    add_emb_k<<<cdiv((long long)N2 * NH, TB), TB>>>(p2, c2emb, nwgt2, h02, N2);
    cudaMemsetAsync(m2, 0, N2 * 4);
    cudaMemsetAsync(z2, 0, N2 * 4);
    cudaMemsetAsync(msg2, 0, (size_t)N2 * NH * 4);
    edge_logits_k<<<cdiv((long long)E2 * 32, TB), TB>>>(A2, A2 + E2, q2, k2, l2, m2, E2);
    edge_expsum_k<<<cdiv(E2, TB), TB>>>(A2, l2, m2, z2, E2);
    edge_msg_k<<<cdiv((long long)E2 * 32, TB), TB>>>(A2, A2 + E2, l2, z2, h02, msg2, E2);
    combine_k<<<cdiv((long long)N2 * NH, TB), TB>>>(h02, msg2, c2a, c2b, c2, N2 * NH);

    // ---- unpool with skips ----
    unpool_add_k<<<cdiv((long long)N1 * NH, TB), TB>>>(c2, assign1, c1, u1, N1);
    unpool_add_k<<<cdiv((long long)N0 * NH, TB), TB>>>(u1, assign0, gcn, crf, N0);

    // ---- GCN layer 2: out = A0 @ (crf @ W2) + b2 ----
    {
        dim3 g(cdiv(NC, GBN), cdiv(N0, GBM));
        sgemm_k<<<g, TB>>>(crf, gc2_W, hW2, N0, NC, NH);
    }
    init_bias_k<<<cdiv((long long)N0 * NC, TB), TB>>>(out, gc2_b, N0 * NC, NC);
    spmm_scatter40<<<cdiv((long long)E0 * 10, TB), TB>>>(A0, A0 + E0, A0v, hW2, out, E0);
}

// round 3
// speedup vs baseline: 1.3960x; 1.3960x over previous
#include <cuda_runtime.h>
#include <cuda_bf16.h>
#include <cstdio>

// Problem constants
#define N0 100000
#define N1 25000
#define N2 6250
#define E0 1600000
#define E1 400000
#define E2 100000
#define NF 128
#define NH 128
#define NC 40

// ---------------------------------------------------------------------------
// Scratch (device globals — no allocation allowed)
// ---------------------------------------------------------------------------
__device__ __align__(16) float g_xW[(size_t)N0 * NH];     // x @ gc1_W
__device__ __align__(16) float g_p1[(size_t)N1 * NH];     // pooled level 1
__device__ __align__(16) float g_q1[(size_t)N1 * NH];
__device__ __align__(16) float g_k1[(size_t)N1 * NH];
__device__ __align__(16) float g_h01[(size_t)N1 * NH];    // p1 + emb[nwgt1]
__device__ __align__(16) float g_msg1[(size_t)N1 * NH];
__device__ __align__(16) float g_c1[(size_t)N1 * NH];     // crf1 output
__device__ __align__(16) float g_p2[(size_t)N2 * NH];
__device__ __align__(16) float g_q2[(size_t)N2 * NH];
__device__ __align__(16) float g_k2[(size_t)N2 * NH];
__device__ __align__(16) float g_h02[(size_t)N2 * NH];
__device__ __align__(16) float g_msg2[(size_t)N2 * NH];
__device__ __align__(16) float g_c2[(size_t)N2 * NH];
__device__ __align__(16) float g_hW2[(size_t)N0 * NC];    // crf_hidden @ gc2_W
__device__ float g_logit1[E1];
__device__ float g_z1[N1];
__device__ unsigned g_max1[N1];
__device__ float g_logit2[E2];
__device__ float g_z2[N2];
__device__ unsigned g_max2[N2];

// ---------------------------------------------------------------------------
// Helpers
// ---------------------------------------------------------------------------
__device__ __forceinline__ unsigned f2ord(float f) {
    unsigned u = __float_as_uint(f);
    return (u & 0x80000000u) ? ~u : (u | 0x80000000u);
}
__device__ __forceinline__ float ord2f(unsigned u) {
    return __uint_as_float((u & 0x80000000u) ? (u & 0x7FFFFFFFu) : ~u);
}
__device__ __forceinline__ void red_add_v4(float4* addr, float a, float b, float c, float d) {
    asm volatile("red.global.add.v4.f32 [%0], {%1, %2, %3, %4};"
                 :: "l"(addr), "f"(a), "f"(b), "f"(c), "f"(d) : "memory");
}

// ---------------------------------------------------------------------------
// High-throughput SGEMM specialized for N = K = 128.
// C[M,128] = A[M,128] @ B[128,128].  blockIdx.x selects (Ba,Ca) vs (Bb,Cb)
// so paired Q/K projections go out in one launch.
// 128x128 block tile, BK=16, 8x8 per-thread micro-tile, 256 threads.
// ---------------------------------------------------------------------------
#define BM 128
#define BN 128
#define BKK 16
__global__ __launch_bounds__(256, 2)
void gemm_nk128(const float* __restrict__ A,
                const float* __restrict__ Ba, const float* __restrict__ Bb,
                float* __restrict__ Ca, float* __restrict__ Cb, int M) {
    __shared__ float As[BKK][BM + 4];
    __shared__ float Bs[BKK][BN];
    const float* __restrict__ B = (blockIdx.x == 0) ? Ba : Bb;
    float* __restrict__ C = (blockIdx.x == 0) ? Ca : Cb;

    int tid = threadIdx.x;
    int row0 = blockIdx.y * BM;

    int trow = tid >> 4;          // 0..15
    int tcol = tid & 15;          // 0..15

    float acc[8][8] = {};
    float a_reg[8], b_reg[8];

    for (int k0 = 0; k0 < 128; k0 += BKK) {
        // Load A tile (128 rows x 16 k), transposed into As[k][row]
#pragma unroll
        for (int i = 0; i < 2; i++) {
            int idx = tid + i * 256;          // 0..511
            int r = idx >> 2;                  // 0..127
            int kq = idx & 3;                  // which float4 along k
            float4 v = make_float4(0.f, 0.f, 0.f, 0.f);
            int gr = row0 + r;
            if (gr < M)
                v = *(const float4*)(A + (size_t)gr * 128 + k0 + kq * 4);
            As[kq * 4 + 0][r] = v.x;
            As[kq * 4 + 1][r] = v.y;
            As[kq * 4 + 2][r] = v.z;
            As[kq * 4 + 3][r] = v.w;
        }
        // Load B tile (16 k x 128 cols)
#pragma unroll
        for (int i = 0; i < 2; i++) {
            int idx = tid + i * 256;
            int r = idx >> 5;                  // 0..15
            int c4 = idx & 31;                 // 0..31
            float4 v = *(const float4*)(B + (size_t)(k0 + r) * 128 + c4 * 4);
            *(float4*)(&Bs[r][c4 * 4]) = v;
        }
        __syncthreads();
#pragma unroll
        for (int kk = 0; kk < BKK; kk++) {
            *(float4*)(a_reg)     = *(const float4*)(&As[kk][trow * 8]);
            *(float4*)(a_reg + 4) = *(const float4*)(&As[kk][trow * 8 + 4]);
            *(float4*)(b_reg)     = *(const float4*)(&Bs[kk][tcol * 8]);
            *(float4*)(b_reg + 4) = *(const float4*)(&Bs[kk][tcol * 8 + 4]);
#pragma unroll
            for (int i = 0; i < 8; i++)
#pragma unroll
                for (int j = 0; j < 8; j++)
                    acc[i][j] += a_reg[i] * b_reg[j];
        }
        __syncthreads();
    }
#pragma unroll
    for (int i = 0; i < 8; i++) {
        int gr = row0 + trow * 8 + i;
        if (gr >= M) continue;
        float* cp = C + (size_t)gr * 128 + tcol * 8;
        *(float4*)(cp)     = make_float4(acc[i][0], acc[i][1], acc[i][2], acc[i][3]);
        *(float4*)(cp + 4) = make_float4(acc[i][4], acc[i][5], acc[i][6], acc[i][7]);
    }
}

// ---------------------------------------------------------------------------
// GEMM for C[M,40] = A[M,128] @ W[128,40].  W smem-resident; one thread/row,
// 40 register accumulators; W rows read as warp-broadcast LDS.128.
// ---------------------------------------------------------------------------
__global__ __launch_bounds__(128)
void gemm_n40(const float* __restrict__ A, const float* __restrict__ W,
              float* __restrict__ C, int M) {
    __shared__ float Ws[128][40];
    int tid = threadIdx.x;
    for (int i = tid; i < 128 * 40 / 4; i += 128)
        ((float4*)Ws)[i] = ((const float4*)W)[i];
    __syncthreads();
    int row = blockIdx.x * 128 + tid;
    if (row >= M) return;
    const float4* a4 = (const float4*)(A + (size_t)row * 128);
    float acc[40] = {};
    for (int kq = 0; kq < 32; kq++) {
        float4 a = a4[kq];
        float av[4] = {a.x, a.y, a.z, a.w};
#pragma unroll
        for (int j = 0; j < 4; j++) {
            const float4* wr = (const float4*)(&Ws[kq * 4 + j][0]);
            float aj = av[j];
#pragma unroll
            for (int c4 = 0; c4 < 10; c4++) {
                float4 w = wr[c4];
                acc[c4 * 4 + 0] += aj * w.x;
                acc[c4 * 4 + 1] += aj * w.y;
                acc[c4 * 4 + 2] += aj * w.z;
                acc[c4 * 4 + 3] += aj * w.w;
            }
        }
    }
    float* cp = C + (size_t)row * 40;
#pragma unroll
    for (int c4 = 0; c4 < 10; c4++)
        *(float4*)(cp + c4 * 4) =
            make_float4(acc[c4 * 4], acc[c4 * 4 + 1], acc[c4 * 4 + 2], acc[c4 * 4 + 3]);
}

// ---------------------------------------------------------------------------
// Elementwise / init kernels
// ---------------------------------------------------------------------------
__global__ void init_bias_k(float* __restrict__ Y, const float* __restrict__ b,
                            int total, int N) {
    int i = blockIdx.x * blockDim.x + threadIdx.x;
    if (i < total) Y[i] = b[i % N];
}
__global__ void relu_k(float* __restrict__ Y, int total4) {
    int i = blockIdx.x * blockDim.x + threadIdx.x;
    if (i >= total4) return;
    float4 v = ((float4*)Y)[i];
    v.x = fmaxf(v.x, 0.f); v.y = fmaxf(v.y, 0.f);
    v.z = fmaxf(v.z, 0.f); v.w = fmaxf(v.w, 0.f);
    ((float4*)Y)[i] = v;
}
__global__ void add_emb_k(const float* __restrict__ X, const float* __restrict__ emb,
                          const int* __restrict__ nw, float* __restrict__ H0, int M) {
    int i = blockIdx.x * blockDim.x + threadIdx.x;
    if (i >= M * 32) return;                  // float4 granularity
    int r = i >> 5, c4 = i & 31;
    float4 x = ((const float4*)X)[i];
    float4 e = ((const float4*)(emb + (size_t)nw[r] * NH))[c4];
    ((float4*)H0)[i] = make_float4(x.x + e.x, x.y + e.y, x.z + e.z, x.w + e.w);
}
__global__ void combine_k(const float* __restrict__ H0, const float* __restrict__ MSG,
                          const float* __restrict__ pa, const float* __restrict__ pb,
                          float* __restrict__ OUT, int total4) {
    int i = blockIdx.x * blockDim.x + threadIdx.x;
    if (i >= total4) return;
    float a = *pa, b = *pb, inv = 1.f / (a + b);
    float4 h = ((const float4*)H0)[i];
    float4 m = ((const float4*)MSG)[i];
    ((float4*)OUT)[i] = make_float4((a * h.x + b * m.x) * inv, (a * h.y + b * m.y) * inv,
                                    (a * h.z + b * m.z) * inv, (a * h.w + b * m.w) * inv);
}
// crf[r] = c2[assign1[assign0[r]]] + c1[assign0[r]] + gcn[r]   (fused unpool)
__global__ void unpool2_k(const float* __restrict__ c2, const float* __restrict__ c1,
                          const float* __restrict__ gcn,
                          const int* __restrict__ assign0, const int* __restrict__ assign1,
                          float* __restrict__ crf) {
    int w = (blockIdx.x * blockDim.x + threadIdx.x) >> 5;
    int lane = threadIdx.x & 31;
    if (w >= N0) return;
    int a0 = assign0[w];
    int a1 = assign1[a0];
    float4 v2 = ((const float4*)(c2 + (size_t)a1 * NH))[lane];
    float4 v1 = ((const float4*)(c1 + (size_t)a0 * NH))[lane];
    float4 vg = ((const float4*)(gcn + (size_t)w * NH))[lane];
    ((float4*)(crf + (size_t)w * NH))[lane] =
        make_float4(v2.x + v1.x + vg.x, v2.y + v1.y + vg.y,
                    v2.z + v1.z + vg.z, v2.w + v1.w + vg.w);
}

// ---------------------------------------------------------------------------
// Scatter kernels (COO SpMM / segment sums via vector reductions)
// ---------------------------------------------------------------------------
__global__ void spmm_scatter128(const int* __restrict__ dsts, const int* __restrict__ srcs,
                                const float* __restrict__ val, const float* __restrict__ X,
                                float* __restrict__ Y, int E) {
    int w = (blockIdx.x * blockDim.x + threadIdx.x) >> 5;
    int lane = threadIdx.x & 31;
    if (w >= E) return;
    int dst = dsts[w], src = srcs[w];
    float v = val[w];
    float4 a = ((const float4*)(X + (size_t)src * NH))[lane];
    float4* yd = ((float4*)(Y + (size_t)dst * NH)) + lane;
    red_add_v4(yd, a.x * v, a.y * v, a.z * v, a.w * v);
}
__global__ void pool128(const float* __restrict__ X, const int* __restrict__ assign,
                        float* __restrict__ Y, int M) {
    int w = (blockIdx.x * blockDim.x + threadIdx.x) >> 5;
    int lane = threadIdx.x & 31;
    if (w >= M) return;
    int dst = assign[w];
    float4 a = ((const float4*)(X + (size_t)w * NH))[lane];
    float4* yd = ((float4*)(Y + (size_t)dst * NH)) + lane;
    red_add_v4(yd, a.x, a.y, a.z, a.w);
}
__global__ void spmm_scatter40(const int* __restrict__ dsts, const int* __restrict__ srcs,
                               const float* __restrict__ val, const float* __restrict__ X,
                               float* __restrict__ Y, int E) {
    int t = blockIdx.x * blockDim.x + threadIdx.x;
    if (t >= E * 10) return;
    int e = t / 10, c = t - e * 10;
    int dst = dsts[e], src = srcs[e];
    float v = val[e];
    float4 a = ((const float4*)(X + (size_t)src * NC))[c];
    float4* yd = ((float4*)(Y + (size_t)dst * NC)) + c;
    red_add_v4(yd, a.x * v, a.y * v, a.z * v, a.w * v);
}

// ---------------------------------------------------------------------------
// CRF edge kernels
// ---------------------------------------------------------------------------
__global__ void edge_logits_k(const int* __restrict__ dsts, const int* __restrict__ srcs,
                              const float* __restrict__ Q, const float* __restrict__ Km,
                              float* __restrict__ logit, unsigned* __restrict__ mx, int E) {
    int w = (blockIdx.x * blockDim.x + threadIdx.x) >> 5;
    int lane = threadIdx.x & 31;
    if (w >= E) return;
    int dst = dsts[w], src = srcs[w];
    float4 q = ((const float4*)(Q + (size_t)dst * NH))[lane];
    float4 k = ((const float4*)(Km + (size_t)src * NH))[lane];
    float acc = q.x * k.x + q.y * k.y + q.z * k.z + q.w * k.w;
#pragma unroll
    for (int o = 16; o; o >>= 1) acc += __shfl_xor_sync(0xFFFFFFFFu, acc, o);
    if (lane == 0) {
        float l = acc * 0.08838834764831845f;   // 1/sqrt(128)
        logit[w] = l;
        atomicMax(mx + dst, f2ord(l));
    }
}
__global__ void edge_expsum_k(const int* __restrict__ dsts, float* __restrict__ logit,
                              const unsigned* __restrict__ mx, float* __restrict__ z, int E) {
    int e = blockIdx.x * blockDim.x + threadIdx.x;
    if (e >= E) return;
    int dst = dsts[e];
    float m = ord2f(mx[dst]);
    float ex = __expf(logit[e] - m);
    logit[e] = ex;
    atomicAdd(z + dst, ex);
}
__global__ void edge_msg_k(const int* __restrict__ dsts, const int* __restrict__ srcs,
                           const float* __restrict__ ev, const float* __restrict__ z,
                           const float* __restrict__ H0, float* __restrict__ MSG, int E) {
    int w = (blockIdx.x * blockDim.x + threadIdx.x) >> 5;
    int lane = threadIdx.x & 31;
    if (w >= E) return;
    int dst = dsts[w], src = srcs[w];
    float c = ev[w] / (z[dst] + 1e-16f);
    float4 a = ((const float4*)(H0 + (size_t)src * NH))[lane];
    float4* yd = ((float4*)(MSG + (size_t)dst * NH)) + lane;
    red_add_v4(yd, a.x * c, a.y * c, a.z * c, a.w * c);
}

// ---------------------------------------------------------------------------
// Host launch
// ---------------------------------------------------------------------------
static inline int cdiv(long long a, long long b) { return (int)((a + b - 1) / b); }

extern "C" void kernel_launch(void* const* d_in, const int* in_sizes, int n_in,
                              void* d_out, int out_size) {
    const float* x       = (const float*)d_in[0];
    const int*   A0      = (const int*)d_in[1];
    const float* A0v     = (const float*)d_in[2];
    const int*   A1      = (const int*)d_in[3];
    const float* A1v     = (const float*)d_in[4];
    const int*   A2      = (const int*)d_in[5];
    const float* A2v     = (const float*)d_in[6];
    const int*   assign0 = (const int*)d_in[7];
    const int*   assign1 = (const int*)d_in[8];
    const int*   nwgt1   = (const int*)d_in[9];
    const int*   nwgt2   = (const int*)d_in[10];
    const float* gc1_W   = (const float*)d_in[11];
    const float* gc1_b   = (const float*)d_in[12];
    const float* gc2_W   = (const float*)d_in[13];
    const float* gc2_b   = (const float*)d_in[14];
    const float* c1Wq    = (const float*)d_in[15];
    const float* c1Wk    = (const float*)d_in[16];
    const float* c1emb   = (const float*)d_in[17];
    const float* c1a     = (const float*)d_in[18];
    const float* c1b     = (const float*)d_in[19];
    const float* c2Wq    = (const float*)d_in[20];
    const float* c2Wk    = (const float*)d_in[21];
    const float* c2emb   = (const float*)d_in[22];
    const float* c2a     = (const float*)d_in[23];
    const float* c2b     = (const float*)d_in[24];

    float* out = (float*)d_out;                       // [N0, NC]
    float* gcn = out + (size_t)N0 * NC;               // [N0, NH] gcn_hidden
    float* crf = gcn + (size_t)N0 * NH;               // [N0, NH] crf_hidden

    void *p_xW, *p_p1, *p_q1, *p_k1, *p_h01, *p_msg1, *p_c1;
    void *p_p2, *p_q2, *p_k2, *p_h02, *p_msg2, *p_c2, *p_hW2;
    void *p_l1, *p_z1, *p_m1, *p_l2, *p_z2, *p_m2;
    cudaGetSymbolAddress(&p_xW, g_xW);   cudaGetSymbolAddress(&p_p1, g_p1);
    cudaGetSymbolAddress(&p_q1, g_q1);   cudaGetSymbolAddress(&p_k1, g_k1);
    cudaGetSymbolAddress(&p_h01, g_h01); cudaGetSymbolAddress(&p_msg1, g_msg1);
    cudaGetSymbolAddress(&p_c1, g_c1);
    cudaGetSymbolAddress(&p_p2, g_p2);   cudaGetSymbolAddress(&p_q2, g_q2);
    cudaGetSymbolAddress(&p_k2, g_k2);   cudaGetSymbolAddress(&p_h02, g_h02);
    cudaGetSymbolAddress(&p_msg2, g_msg2); cudaGetSymbolAddress(&p_c2, g_c2);
    cudaGetSymbolAddress(&p_hW2, g_hW2);
    cudaGetSymbolAddress(&p_l1, g_logit1); cudaGetSymbolAddress(&p_z1, g_z1);
    cudaGetSymbolAddress(&p_m1, g_max1);
    cudaGetSymbolAddress(&p_l2, g_logit2); cudaGetSymbolAddress(&p_z2, g_z2);
    cudaGetSymbolAddress(&p_m2, g_max2);

    float* xW  = (float*)p_xW;  float* p1 = (float*)p_p1;  float* q1 = (float*)p_q1;
    float* k1  = (float*)p_k1;  float* h01 = (float*)p_h01; float* msg1 = (float*)p_msg1;
    float* c1  = (float*)p_c1;
    float* p2  = (float*)p_p2;  float* q2 = (float*)p_q2;  float* k2 = (float*)p_k2;
    float* h02 = (float*)p_h02; float* msg2 = (float*)p_msg2; float* c2 = (float*)p_c2;
    float* hW2 = (float*)p_hW2;
    float* l1 = (float*)p_l1; float* z1 = (float*)p_z1; unsigned* m1 = (unsigned*)p_m1;
    float* l2 = (float*)p_l2; float* z2 = (float*)p_z2; unsigned* m2 = (unsigned*)p_m2;

    const int TB = 256;

    // ---- GCN layer 1: gcn = relu(A0 @ (x @ W1) + b1) ----
    {
        dim3 g(1, cdiv(N0, BM));
        gemm_nk128<<<g, 256>>>(x, gc1_W, gc1_W, xW, xW, N0);
    }
    init_bias_k<<<cdiv((long long)N0 * NH, TB), TB>>>(gcn, gc1_b, N0 * NH, NH);
    spmm_scatter128<<<cdiv((long long)E0 * 32, TB), TB>>>(A0, A0 + E0, A0v, xW, gcn, E0);
    relu_k<<<cdiv((long long)N0 * NH / 4, TB), TB>>>(gcn, N0 * NH / 4);

    // ---- level 1: pool + CRF ----
    cudaMemsetAsync(p1, 0, (size_t)N1 * NH * 4);
    pool128<<<cdiv((long long)N0 * 32, TB), TB>>>(gcn, assign0, p1, N0);
    {
        dim3 g(2, cdiv(N1, BM));
        gemm_nk128<<<g, 256>>>(p1, c1Wq, c1Wk, q1, k1, N1);
    }
    add_emb_k<<<cdiv((long long)N1 * 32, TB), TB>>>(p1, c1emb, nwgt1, h01, N1);
    cudaMemsetAsync(m1, 0, N1 * 4);
    cudaMemsetAsync(z1, 0, N1 * 4);
    cudaMemsetAsync(msg1, 0, (size_t)N1 * NH * 4);
    edge_logits_k<<<cdiv((long long)E1 * 32, TB), TB>>>(A1, A1 + E1, q1, k1, l1, m1, E1);
    edge_expsum_k<<<cdiv(E1, TB), TB>>>(A1, l1, m1, z1, E1);
    edge_msg_k<<<cdiv((long long)E1 * 32, TB), TB>>>(A1, A1 + E1, l1, z1, h01, msg1, E1);
    combine_k<<<cdiv((long long)N1 * NH / 4, TB), TB>>>(h01, msg1, c1a, c1b, c1, N1 * NH / 4);

    // ---- level 2: pool + CRF ----
    cudaMemsetAsync(p2, 0, (size_t)N2 * NH * 4);
    pool128<<<cdiv((long long)N1 * 32, TB), TB>>>(c1, assign1, p2, N1);
    {
        dim3 g(2, cdiv(N2, BM));
        gemm_nk128<<<g, 256>>>(p2, c2Wq, c2Wk, q2, k2, N2);
    }
    add_emb_k<<<cdiv((long long)N2 * 32, TB), TB>>>(p2, c2emb, nwgt2, h02, N2);
    cudaMemsetAsync(m2, 0, N2 * 4);
    cudaMemsetAsync(z2, 0, N2 * 4);
    cudaMemsetAsync(msg2, 0, (size_t)N2 * NH * 4);
    edge_logits_k<<<cdiv((long long)E2 * 32, TB), TB>>>(A2, A2 + E2, q2, k2, l2, m2, E2);
    edge_expsum_k<<<cdiv(E2, TB), TB>>>(A2, l2, m2, z2, E2);
    edge_msg_k<<<cdiv((long long)E2 * 32, TB), TB>>>(A2, A2 + E2, l2, z2, h02, msg2, E2);
    combine_k<<<cdiv((long long)N2 * NH / 4, TB), TB>>>(h02, msg2, c2a, c2b, c2, N2 * NH / 4);

    // ---- fused unpool with skips: crf = c2[a1[a0]] + c1[a0] + gcn ----
    unpool2_k<<<cdiv((long long)N0 * 32, TB), TB>>>(c2, c1, gcn, assign0, assign1, crf);

    // ---- GCN layer 2: out = A0 @ (crf @ W2) + b2 ----
    gemm_n40<<<cdiv(N0, 128), 128>>>(crf, gc2_W, hW2, N0);
    init_bias_k<<<cdiv((long long)N0 * NC, TB), TB>>>(out, gc2_b, N0 * NC, NC);
    spmm_scatter40<<<cdiv((long long)E0 * 10, TB), TB>>>(A0, A0 + E0, A0v, hW2, out, E0);
}